// round 3
// baseline (speedup 1.0000x reference)
#include <cuda_runtime.h>
#include <cstdint>

#define N_USERS 100000
#define N_ITEMS 200000
#define N_NODES 300000   // N_USERS + N_ITEMS
#define DIM 64
#define N_EDGES 3200000
#define N_LAYERS 3

// Scratch ping-pong buffers for layer outputs (76.8 MB each).
__device__ float g_bufA[(size_t)N_NODES * DIM];
__device__ float g_bufB[(size_t)N_NODES * DIM];

// ---------------------------------------------------------------------------
// SpMM scatter: y[rows[e]] += vals[e] * x[cols[e]]  (row = 64 floats)
// 16 threads per edge, each owns one float4 chunk (16 B).
// Gather: 256 B contiguous per edge (coalesced across the 16 threads).
// Scatter: red.global.add.v4.f32 (no return trip), 16 B per thread.
// ---------------------------------------------------------------------------
__global__ void __launch_bounds__(512) spmm_kernel(
    const float* __restrict__ x, float* __restrict__ y,
    const int* __restrict__ rows, const int* __restrict__ cols,
    const float* __restrict__ vals)
{
    long long gid = (long long)blockIdx.x * blockDim.x + threadIdx.x;
    int e = (int)(gid >> 4);
    if (e >= N_EDGES) return;
    int c = (int)(gid & 15);

    int col = __ldg(&cols[e]);
    int row = __ldg(&rows[e]);
    float v = __ldg(&vals[e]);

    const float4* xp = reinterpret_cast<const float4*>(x) + ((long long)col * 16 + c);
    float4 xv = __ldg(xp);
    xv.x *= v; xv.y *= v; xv.z *= v; xv.w *= v;

    float* yp = y + (((long long)row * 16 + c) << 2);
#if defined(__CUDA_ARCH__) && (__CUDA_ARCH__ >= 900)
    asm volatile("red.global.add.v4.f32 [%0], {%1, %2, %3, %4};"
                 :: "l"(yp), "f"(xv.x), "f"(xv.y), "f"(xv.z), "f"(xv.w)
                 : "memory");
#else
    atomicAdd(yp + 0, xv.x);
    atomicAdd(yp + 1, xv.y);
    atomicAdd(yp + 2, xv.z);
    atomicAdd(yp + 3, xv.w);
#endif
}

// ---------------------------------------------------------------------------
// acc: out = (out + y) * scale   (scale = 1.0 for layers 0,1; 0.25 for last)
// ---------------------------------------------------------------------------
__global__ void __launch_bounds__(256) acc_kernel(
    float* __restrict__ out, const float* __restrict__ y, float scale)
{
    int i = blockIdx.x * blockDim.x + threadIdx.x;
    const int n4 = N_NODES * (DIM / 4);
    if (i >= n4) return;
    float4 o = reinterpret_cast<float4*>(out)[i];
    float4 a = reinterpret_cast<const float4*>(y)[i];
    o.x = (o.x + a.x) * scale;
    o.y = (o.y + a.y) * scale;
    o.z = (o.z + a.z) * scale;
    o.w = (o.w + a.w) * scale;
    reinterpret_cast<float4*>(out)[i] = o;
}

extern "C" void kernel_launch(void* const* d_in, const int* in_sizes, int n_in,
                              void* d_out, int out_size)
{
    const float* user_emb = (const float*)d_in[0];
    const float* item_emb = (const float*)d_in[1];
    const int*   rows     = (const int*)d_in[2];
    const int*   cols     = (const int*)d_in[3];
    const float* vals     = (const float*)d_in[4];
    // d_in[5] = n_layers (fixed at 3 by setup_inputs; not readable without a
    // synchronous copy, so compiled in as N_LAYERS).
    (void)in_sizes; (void)n_in; (void)out_size;

    float* out = (float*)d_out;

    float *A = nullptr, *B = nullptr;
    cudaGetSymbolAddress((void**)&A, g_bufA);
    cudaGetSymbolAddress((void**)&B, g_bufB);

    const size_t user_bytes = (size_t)N_USERS * DIM * sizeof(float);
    const size_t item_bytes = (size_t)N_ITEMS * DIM * sizeof(float);
    const size_t node_bytes = (size_t)N_NODES * DIM * sizeof(float);

    // out <- concat(user_emb, item_emb). This is both acc's initial value
    // (x0 term) and the layer-0 SpMM input.
    cudaMemcpyAsync(out, user_emb, user_bytes, cudaMemcpyDeviceToDevice);
    cudaMemcpyAsync(out + (size_t)N_USERS * DIM, item_emb, item_bytes,
                    cudaMemcpyDeviceToDevice);

    const int spmm_threads = 512;
    const long long spmm_total = (long long)N_EDGES * 16;
    const int spmm_blocks = (int)((spmm_total + spmm_threads - 1) / spmm_threads);

    const int acc_threads = 256;
    const int acc_n4 = N_NODES * (DIM / 4);
    const int acc_blocks = (acc_n4 + acc_threads - 1) / acc_threads;

    // ---- Layer 0: x = out (concat) -> y = A; acc: out += A
    cudaMemsetAsync(A, 0, node_bytes);
    spmm_kernel<<<spmm_blocks, spmm_threads>>>(out, A, rows, cols, vals);
    acc_kernel<<<acc_blocks, acc_threads>>>(out, A, 1.0f);

    // ---- Layer 1: x = A -> y = B; acc: out += B
    cudaMemsetAsync(B, 0, node_bytes);
    spmm_kernel<<<spmm_blocks, spmm_threads>>>(A, B, rows, cols, vals);
    acc_kernel<<<acc_blocks, acc_threads>>>(out, B, 1.0f);

    // ---- Layer 2: x = B -> y = A (A's old contents dead); acc folds the /4
    cudaMemsetAsync(A, 0, node_bytes);
    spmm_kernel<<<spmm_blocks, spmm_threads>>>(B, A, rows, cols, vals);
    acc_kernel<<<acc_blocks, acc_threads>>>(out, A, 0.25f);
}

// round 5
// speedup vs baseline: 1.8661x; 1.8661x over previous
#include <cuda_runtime.h>
#include <cstdint>

#define N_USERS 100000
#define N_ITEMS 200000
#define N_NODES 300000   // N_USERS + N_ITEMS
#define DIM 64
#define N_EDGES 3200000
#define N_LAYERS 3

#define SCAN_BLOCK 1024
#define N_SCAN_BLOCKS ((N_NODES + SCAN_BLOCK - 1) / SCAN_BLOCK)   // 293

// Node-embedding buffers (76.8 MB each)
__device__ float g_bufA[(size_t)N_NODES * DIM];
__device__ float g_bufB[(size_t)N_NODES * DIM];
__device__ float g_bufC[(size_t)N_NODES * DIM];   // holds x0 = concat(user,item)

// CSR build scratch
__device__ int   g_counts[N_NODES];
__device__ int   g_partial[N_NODES];          // in-block exclusive scan
__device__ int   g_blockSums[N_SCAN_BLOCKS];
__device__ int   g_blockOffs[N_SCAN_BLOCKS];
__device__ int   g_rowptr[N_NODES + 1];
__device__ int   g_cursor[N_NODES];
__device__ int   g_colidx[N_EDGES];
__device__ float g_sval[N_EDGES];

// ---------------------------------------------------------------------------
// CSR build: histogram of row ids
// ---------------------------------------------------------------------------
__global__ void __launch_bounds__(256) hist_kernel(const int* __restrict__ rows)
{
    int e = blockIdx.x * blockDim.x + threadIdx.x;
    if (e >= N_EDGES) return;
    atomicAdd(&g_counts[__ldg(&rows[e])], 1);
}

// ---------------------------------------------------------------------------
// Scan stage 1: per-block inclusive scan of counts -> exclusive + block totals
// ---------------------------------------------------------------------------
__global__ void __launch_bounds__(SCAN_BLOCK) scan1_kernel()
{
    __shared__ int sh[SCAN_BLOCK];
    int i = blockIdx.x * SCAN_BLOCK + threadIdx.x;
    int v = (i < N_NODES) ? g_counts[i] : 0;
    sh[threadIdx.x] = v;
    __syncthreads();
    for (int off = 1; off < SCAN_BLOCK; off <<= 1) {
        int t = (threadIdx.x >= off) ? sh[threadIdx.x - off] : 0;
        __syncthreads();
        sh[threadIdx.x] += t;
        __syncthreads();
    }
    int incl = sh[threadIdx.x];
    if (i < N_NODES) g_partial[i] = incl - v;           // exclusive
    if (threadIdx.x == SCAN_BLOCK - 1) g_blockSums[blockIdx.x] = incl;
}

// ---------------------------------------------------------------------------
// Scan stage 2: single-block exclusive scan of the 293 block sums
// ---------------------------------------------------------------------------
__global__ void __launch_bounds__(512) scan2_kernel()
{
    __shared__ int sh[512];
    int v = (threadIdx.x < N_SCAN_BLOCKS) ? g_blockSums[threadIdx.x] : 0;
    sh[threadIdx.x] = v;
    __syncthreads();
    for (int off = 1; off < 512; off <<= 1) {
        int t = (threadIdx.x >= off) ? sh[threadIdx.x - off] : 0;
        __syncthreads();
        sh[threadIdx.x] += t;
        __syncthreads();
    }
    if (threadIdx.x < N_SCAN_BLOCKS) g_blockOffs[threadIdx.x] = sh[threadIdx.x] - v;
}

// ---------------------------------------------------------------------------
// Scan stage 3: rowptr = partial + blockOffs; cursor = rowptr
// ---------------------------------------------------------------------------
__global__ void __launch_bounds__(256) scan3_kernel()
{
    int i = blockIdx.x * blockDim.x + threadIdx.x;
    if (i < N_NODES) {
        int r = g_partial[i] + g_blockOffs[i / SCAN_BLOCK];
        g_rowptr[i] = r;
        g_cursor[i] = r;
    }
    if (i == 0) g_rowptr[N_NODES] = N_EDGES;
}

// ---------------------------------------------------------------------------
// CSR build: scatter edges into row-sorted order
// ---------------------------------------------------------------------------
__global__ void __launch_bounds__(256) edge_scatter_kernel(
    const int* __restrict__ rows, const int* __restrict__ cols,
    const float* __restrict__ vals)
{
    int e = blockIdx.x * blockDim.x + threadIdx.x;
    if (e >= N_EDGES) return;
    int r = __ldg(&rows[e]);
    int pos = atomicAdd(&g_cursor[r], 1);
    g_colidx[pos] = __ldg(&cols[e]);
    g_sval[pos]   = __ldg(&vals[e]);
}

// ---------------------------------------------------------------------------
// CSR SpMM with fused accumulate: one warp per row, float2 per lane.
//   s        = sum_j v_j * x[col_j]          (row of the new layer)
//   y[row]   = s                             (if writeY)
//   out[row] = (base[row] + s) * scale       (base = C for layer0, else out)
// No atomics, no memset; each warp exclusively owns its output row.
// ---------------------------------------------------------------------------
__global__ void __launch_bounds__(256) spmm_csr_fused(
    const float* __restrict__ x, float* __restrict__ y,
    const float* __restrict__ base, float* __restrict__ out,
    float scale, int writeY)
{
    int warp = (blockIdx.x * blockDim.x + threadIdx.x) >> 5;
    if (warp >= N_NODES) return;
    int lane = threadIdx.x & 31;

    int beg = __ldg(&g_rowptr[warp]);
    int end = __ldg(&g_rowptr[warp + 1]);

    float sx = 0.f, sy = 0.f;
    const float2* x2 = reinterpret_cast<const float2*>(x);
    for (int j = beg; j < end; ++j) {
        int   col = __ldg(&g_colidx[j]);
        float v   = __ldg(&g_sval[j]);
        float2 xv = __ldg(x2 + (((long long)col << 5) + lane));
        sx += v * xv.x;
        sy += v * xv.y;
    }

    long long o = ((long long)warp << 5) + lane;
    if (writeY) {
        float2 s2; s2.x = sx; s2.y = sy;
        reinterpret_cast<float2*>(y)[o] = s2;
    }
    float2 b = __ldg(reinterpret_cast<const float2*>(base) + o);
    float2 r;
    r.x = (b.x + sx) * scale;
    r.y = (b.y + sy) * scale;
    reinterpret_cast<float2*>(out)[o] = r;
}

extern "C" void kernel_launch(void* const* d_in, const int* in_sizes, int n_in,
                              void* d_out, int out_size)
{
    const float* user_emb = (const float*)d_in[0];
    const float* item_emb = (const float*)d_in[1];
    const int*   rows     = (const int*)d_in[2];
    const int*   cols     = (const int*)d_in[3];
    const float* vals     = (const float*)d_in[4];
    // d_in[5] = n_layers, fixed at 3 (compiled in as N_LAYERS)
    (void)in_sizes; (void)n_in; (void)out_size;

    float* out = (float*)d_out;

    float *A, *B, *C;
    int* counts;
    cudaGetSymbolAddress((void**)&A, g_bufA);
    cudaGetSymbolAddress((void**)&B, g_bufB);
    cudaGetSymbolAddress((void**)&C, g_bufC);
    cudaGetSymbolAddress((void**)&counts, g_counts);

    const size_t user_bytes = (size_t)N_USERS * DIM * sizeof(float);
    const size_t item_bytes = (size_t)N_ITEMS * DIM * sizeof(float);

    // ---- CSR build ----
    cudaMemsetAsync(counts, 0, N_NODES * sizeof(int));
    {
        const int t = 256, b = (N_EDGES + t - 1) / t;
        hist_kernel<<<b, t>>>(rows);
    }
    scan1_kernel<<<N_SCAN_BLOCKS, SCAN_BLOCK>>>();
    scan2_kernel<<<1, 512>>>();
    {
        const int t = 256, b = (N_NODES + t - 1) / t;
        scan3_kernel<<<b, t>>>();
    }
    {
        const int t = 256, b = (N_EDGES + t - 1) / t;
        edge_scatter_kernel<<<b, t>>>(rows, cols, vals);
    }

    // ---- x0 = concat(user, item) into C ----
    cudaMemcpyAsync(C, user_emb, user_bytes, cudaMemcpyDeviceToDevice);
    cudaMemcpyAsync(C + (size_t)N_USERS * DIM, item_emb, item_bytes,
                    cudaMemcpyDeviceToDevice);

    const int spmm_threads = 256;
    const long long spmm_total = (long long)N_NODES * 32;
    const int spmm_blocks = (int)((spmm_total + spmm_threads - 1) / spmm_threads);

    // Layer 0: x=C -> y=A;  out = C + A
    spmm_csr_fused<<<spmm_blocks, spmm_threads>>>(C, A, C, out, 1.0f, 1);
    // Layer 1: x=A -> y=B;  out = out + B
    spmm_csr_fused<<<spmm_blocks, spmm_threads>>>(A, B, out, out, 1.0f, 1);
    // Layer 2: x=B -> (no y); out = (out + s) / 4
    spmm_csr_fused<<<spmm_blocks, spmm_threads>>>(B, nullptr, out, out, 0.25f, 0);
}

// round 8
// speedup vs baseline: 1.9611x; 1.0509x over previous
#include <cuda_runtime.h>
#include <cuda_fp16.h>
#include <cstdint>

#define N_USERS 100000
#define N_ITEMS 200000
#define N_NODES 300000   // N_USERS + N_ITEMS
#define DIM 64
#define N_EDGES 3200000
#define N_LAYERS 3

#define SCAN_BLOCK 1024
#define N_SCAN_BLOCKS ((N_NODES + SCAN_BLOCK - 1) / SCAN_BLOCK)   // 293

// Half-precision ping-pong node buffers (38.4 MB each — L2-resident)
__device__ __half2 g_h0[(size_t)N_NODES * (DIM / 2)];
__device__ __half2 g_h1[(size_t)N_NODES * (DIM / 2)];

// CSR build scratch
__device__ int   g_counts[N_NODES];
__device__ int   g_partial[N_NODES];
__device__ int   g_blockSums[N_SCAN_BLOCKS];
__device__ int   g_blockOffs[N_SCAN_BLOCKS];
__device__ int   g_rowptr[N_NODES + 1];
__device__ int   g_cursor[N_NODES];
__device__ int2  g_edges[N_EDGES];    // {col, __float_as_int(val)} packed

// ---------------------------------------------------------------------------
// CSR build: histogram of row ids
// ---------------------------------------------------------------------------
__global__ void __launch_bounds__(256) hist_kernel(const int* __restrict__ rows)
{
    int e = blockIdx.x * blockDim.x + threadIdx.x;
    if (e >= N_EDGES) return;
    atomicAdd(&g_counts[__ldg(&rows[e])], 1);
}

// ---------------------------------------------------------------------------
// Scan stage 1: per-block scan of counts -> exclusive partials + block totals
// ---------------------------------------------------------------------------
__global__ void __launch_bounds__(SCAN_BLOCK) scan1_kernel()
{
    __shared__ int sh[SCAN_BLOCK];
    int i = blockIdx.x * SCAN_BLOCK + threadIdx.x;
    int v = (i < N_NODES) ? g_counts[i] : 0;
    sh[threadIdx.x] = v;
    __syncthreads();
    for (int off = 1; off < SCAN_BLOCK; off <<= 1) {
        int t = (threadIdx.x >= off) ? sh[threadIdx.x - off] : 0;
        __syncthreads();
        sh[threadIdx.x] += t;
        __syncthreads();
    }
    int incl = sh[threadIdx.x];
    if (i < N_NODES) g_partial[i] = incl - v;
    if (threadIdx.x == SCAN_BLOCK - 1) g_blockSums[blockIdx.x] = incl;
}

// ---------------------------------------------------------------------------
// Scan stage 2: single-block exclusive scan of the 293 block sums
// ---------------------------------------------------------------------------
__global__ void __launch_bounds__(512) scan2_kernel()
{
    __shared__ int sh[512];
    int v = (threadIdx.x < N_SCAN_BLOCKS) ? g_blockSums[threadIdx.x] : 0;
    sh[threadIdx.x] = v;
    __syncthreads();
    for (int off = 1; off < 512; off <<= 1) {
        int t = (threadIdx.x >= off) ? sh[threadIdx.x - off] : 0;
        __syncthreads();
        sh[threadIdx.x] += t;
        __syncthreads();
    }
    if (threadIdx.x < N_SCAN_BLOCKS) g_blockOffs[threadIdx.x] = sh[threadIdx.x] - v;
}

// ---------------------------------------------------------------------------
// Scan stage 3: rowptr = partial + blockOffs; cursor = rowptr
// ---------------------------------------------------------------------------
__global__ void __launch_bounds__(256) scan3_kernel()
{
    int i = blockIdx.x * blockDim.x + threadIdx.x;
    if (i < N_NODES) {
        int r = g_partial[i] + g_blockOffs[i / SCAN_BLOCK];
        g_rowptr[i] = r;
        g_cursor[i] = r;
    }
    if (i == 0) g_rowptr[N_NODES] = N_EDGES;
}

// ---------------------------------------------------------------------------
// CSR build: scatter edges (packed {col,val}) into row-sorted order
// ---------------------------------------------------------------------------
__global__ void __launch_bounds__(256) edge_scatter_kernel(
    const int* __restrict__ rows, const int* __restrict__ cols,
    const float* __restrict__ vals)
{
    int e = blockIdx.x * blockDim.x + threadIdx.x;
    if (e >= N_EDGES) return;
    int r = __ldg(&rows[e]);
    int pos = atomicAdd(&g_cursor[r], 1);
    int2 cv;
    cv.x = __ldg(&cols[e]);
    cv.y = __float_as_int(__ldg(&vals[e]));
    g_edges[pos] = cv;     // single 8B random store
}

// ---------------------------------------------------------------------------
// Concat + fp16 snapshot: out <- concat(user,item) fp32; h <- same in half2.
// Replaces the two D2D memcpys and buffer C.
// ---------------------------------------------------------------------------
__global__ void __launch_bounds__(256) concat_kernel(
    const float* __restrict__ user_emb, const float* __restrict__ item_emb,
    float* __restrict__ out, __half2* __restrict__ h)
{
    int i = blockIdx.x * blockDim.x + threadIdx.x;   // float2 index
    const int n2 = N_NODES * (DIM / 2);
    if (i >= n2) return;
    const int nu2 = N_USERS * (DIM / 2);
    float2 v = (i < nu2)
        ? reinterpret_cast<const float2*>(user_emb)[i]
        : reinterpret_cast<const float2*>(item_emb)[i - nu2];
    reinterpret_cast<float2*>(out)[i] = v;
    h[i] = __floats2half2_rn(v.x, v.y);
}

// ---------------------------------------------------------------------------
// CSR SpMM (half2 gather, fp32 accumulate) with fused accumulate epilogue.
// One warp per row, one half2 (2 dims) per lane.
// Edge metadata for j+1 is prefetched while gather j is outstanding (MLP=2
// on the dependent chain; helps if the loop is latency-bound).
//   s        = sum_j v_j * x[col_j]      (fp32 accum from half2 gather)
//   yh[row]  = half(s)                   (if writeY — next layer's input)
//   out[row] = (out[row] + s) * scale
// ---------------------------------------------------------------------------
__global__ void __launch_bounds__(256) spmm_csr_fused(
    const __half2* __restrict__ xh, __half2* __restrict__ yh,
    float* __restrict__ out, float scale, int writeY)
{
    int warp = (blockIdx.x * blockDim.x + threadIdx.x) >> 5;
    if (warp >= N_NODES) return;
    int lane = threadIdx.x & 31;

    int beg = __ldg(&g_rowptr[warp]);
    int end = __ldg(&g_rowptr[warp + 1]);

    float sx = 0.f, sy = 0.f;
    if (beg < end) {
        int2 cv = __ldg(&g_edges[beg]);
        for (int j = beg; j < end; ++j) {
            // issue the gather for the current edge
            __half2 xv = __ldg(xh + (((long long)cv.x << 5) + lane));
            float v = __int_as_float(cv.y);
            // prefetch next edge metadata while the gather is in flight
            if (j + 1 < end) cv = __ldg(&g_edges[j + 1]);
            float2 xf = __half22float2(xv);
            sx += v * xf.x;
            sy += v * xf.y;
        }
    }

    long long o = ((long long)warp << 5) + lane;
    if (writeY) yh[o] = __floats2half2_rn(sx, sy);

    float2 b = reinterpret_cast<float2*>(out)[o];
    float2 r;
    r.x = (b.x + sx) * scale;
    r.y = (b.y + sy) * scale;
    reinterpret_cast<float2*>(out)[o] = r;
}

extern "C" void kernel_launch(void* const* d_in, const int* in_sizes, int n_in,
                              void* d_out, int out_size)
{
    const float* user_emb = (const float*)d_in[0];
    const float* item_emb = (const float*)d_in[1];
    const int*   rows     = (const int*)d_in[2];
    const int*   cols     = (const int*)d_in[3];
    const float* vals     = (const float*)d_in[4];
    // d_in[5] = n_layers, fixed at 3 (compiled in as N_LAYERS)
    (void)in_sizes; (void)n_in; (void)out_size;

    float* out = (float*)d_out;

    __half2 *H0, *H1;
    int* counts;
    cudaGetSymbolAddress((void**)&H0, g_h0);
    cudaGetSymbolAddress((void**)&H1, g_h1);
    cudaGetSymbolAddress((void**)&counts, g_counts);

    // ---- CSR build ----
    cudaMemsetAsync(counts, 0, N_NODES * sizeof(int));
    {
        const int t = 256, b = (N_EDGES + t - 1) / t;
        hist_kernel<<<b, t>>>(rows);
    }
    scan1_kernel<<<N_SCAN_BLOCKS, SCAN_BLOCK>>>();
    scan2_kernel<<<1, 512>>>();
    {
        const int t = 256, b = (N_NODES + t - 1) / t;
        scan3_kernel<<<b, t>>>();
    }
    {
        const int t = 256, b = (N_EDGES + t - 1) / t;
        edge_scatter_kernel<<<b, t>>>(rows, cols, vals);
    }

    // ---- x0: out <- concat (fp32), H0 <- concat (half) ----
    {
        const int n2 = N_NODES * (DIM / 2);
        const int t = 256, b = (n2 + t - 1) / t;
        concat_kernel<<<b, t>>>(user_emb, item_emb, out, H0);
    }

    const int spmm_threads = 256;
    const long long spmm_total = (long long)N_NODES * 32;
    const int spmm_blocks = (int)((spmm_total + spmm_threads - 1) / spmm_threads);

    // Layer 0: gather H0 -> y H1;  out = out + s
    spmm_csr_fused<<<spmm_blocks, spmm_threads>>>(H0, H1, out, 1.0f, 1);
    // Layer 1: gather H1 -> y H0 (H0 dead);  out = out + s
    spmm_csr_fused<<<spmm_blocks, spmm_threads>>>(H1, H0, out, 1.0f, 1);
    // Layer 2: gather H0 -> no y;  out = (out + s) / 4
    spmm_csr_fused<<<spmm_blocks, spmm_threads>>>(H0, nullptr, out, 0.25f, 0);
}

// round 10
// speedup vs baseline: 1.9674x; 1.0032x over previous
#include <cuda_runtime.h>
#include <cuda_fp16.h>
#include <cstdint>

#define N_USERS 100000
#define N_ITEMS 200000
#define N_NODES 300000   // N_USERS + N_ITEMS
#define DIM 64
#define N_EDGES 3200000
#define N_LAYERS 3

#define SCAN_BLOCK 1024
#define N_SCAN_BLOCKS ((N_NODES + SCAN_BLOCK - 1) / SCAN_BLOCK)   // 293

// Half-precision ping-pong node buffers (38.4 MB each — L2-resident)
__device__ __half2 g_h0[(size_t)N_NODES * (DIM / 2)];
__device__ __half2 g_h1[(size_t)N_NODES * (DIM / 2)];

// CSR build scratch
__device__ int   g_counts[N_NODES];
__device__ int   g_partial[N_NODES];
__device__ int   g_blockSums[N_SCAN_BLOCKS];
__device__ int   g_blockOffs[N_SCAN_BLOCKS];
__device__ int   g_rowptr[N_NODES + 1];
__device__ int   g_cursor[N_NODES];
__device__ int2  g_edges[N_EDGES];    // {col, __float_as_int(val)} packed

// ---------------------------------------------------------------------------
// CSR build: histogram of row ids
// ---------------------------------------------------------------------------
__global__ void __launch_bounds__(256) hist_kernel(const int* __restrict__ rows)
{
    int e = blockIdx.x * blockDim.x + threadIdx.x;
    if (e >= N_EDGES) return;
    atomicAdd(&g_counts[__ldg(&rows[e])], 1);
}

// ---------------------------------------------------------------------------
// Scan stage 1: per-block scan of counts -> exclusive partials + block totals
// ---------------------------------------------------------------------------
__global__ void __launch_bounds__(SCAN_BLOCK) scan1_kernel()
{
    __shared__ int sh[SCAN_BLOCK];
    int i = blockIdx.x * SCAN_BLOCK + threadIdx.x;
    int v = (i < N_NODES) ? g_counts[i] : 0;
    sh[threadIdx.x] = v;
    __syncthreads();
    for (int off = 1; off < SCAN_BLOCK; off <<= 1) {
        int t = (threadIdx.x >= off) ? sh[threadIdx.x - off] : 0;
        __syncthreads();
        sh[threadIdx.x] += t;
        __syncthreads();
    }
    int incl = sh[threadIdx.x];
    if (i < N_NODES) g_partial[i] = incl - v;
    if (threadIdx.x == SCAN_BLOCK - 1) g_blockSums[blockIdx.x] = incl;
}

// ---------------------------------------------------------------------------
// Scan stage 2: single-block exclusive scan of the 293 block sums
// ---------------------------------------------------------------------------
__global__ void __launch_bounds__(512) scan2_kernel()
{
    __shared__ int sh[512];
    int v = (threadIdx.x < N_SCAN_BLOCKS) ? g_blockSums[threadIdx.x] : 0;
    sh[threadIdx.x] = v;
    __syncthreads();
    for (int off = 1; off < 512; off <<= 1) {
        int t = (threadIdx.x >= off) ? sh[threadIdx.x - off] : 0;
        __syncthreads();
        sh[threadIdx.x] += t;
        __syncthreads();
    }
    if (threadIdx.x < N_SCAN_BLOCKS) g_blockOffs[threadIdx.x] = sh[threadIdx.x] - v;
}

// ---------------------------------------------------------------------------
// Scan stage 3: rowptr = partial + blockOffs; cursor = rowptr
// ---------------------------------------------------------------------------
__global__ void __launch_bounds__(256) scan3_kernel()
{
    int i = blockIdx.x * blockDim.x + threadIdx.x;
    if (i < N_NODES) {
        int r = g_partial[i] + g_blockOffs[i / SCAN_BLOCK];
        g_rowptr[i] = r;
        g_cursor[i] = r;
    }
    if (i == 0) g_rowptr[N_NODES] = N_EDGES;
}

// ---------------------------------------------------------------------------
// CSR build: scatter edges (packed {col,val}) into row-sorted order
// ---------------------------------------------------------------------------
__global__ void __launch_bounds__(256) edge_scatter_kernel(
    const int* __restrict__ rows, const int* __restrict__ cols,
    const float* __restrict__ vals)
{
    int e = blockIdx.x * blockDim.x + threadIdx.x;
    if (e >= N_EDGES) return;
    int r = __ldg(&rows[e]);
    int pos = atomicAdd(&g_cursor[r], 1);
    int2 cv;
    cv.x = __ldg(&cols[e]);
    cv.y = __float_as_int(__ldg(&vals[e]));
    g_edges[pos] = cv;     // single 8B random store
}

// ---------------------------------------------------------------------------
// Concat + fp16 snapshot: out <- concat(user,item) fp32; h <- same in half2.
// ---------------------------------------------------------------------------
__global__ void __launch_bounds__(256) concat_kernel(
    const float* __restrict__ user_emb, const float* __restrict__ item_emb,
    float* __restrict__ out, __half2* __restrict__ h)
{
    int i = blockIdx.x * blockDim.x + threadIdx.x;   // float2 index
    const int n2 = N_NODES * (DIM / 2);
    if (i >= n2) return;
    const int nu2 = N_USERS * (DIM / 2);
    float2 v = (i < nu2)
        ? reinterpret_cast<const float2*>(user_emb)[i]
        : reinterpret_cast<const float2*>(item_emb)[i - nu2];
    reinterpret_cast<float2*>(out)[i] = v;
    h[i] = __floats2half2_rn(v.x, v.y);
}

// ---------------------------------------------------------------------------
// CSR SpMM (half2 gather, fp32 accumulate) with fused accumulate epilogue.
// One warp per row, one half2 (2 dims) per lane.
// Edge loop unrolled x4: 4 consecutive edge records (one 32B sector) are
// loaded, then 4 INDEPENDENT gathers issued before any FMA consumes them —
// MLP~4 on the dependent chain (R8 post-mortem showed the loop is
// latency-bound, not BW-bound).
// ---------------------------------------------------------------------------
__global__ void __launch_bounds__(256) spmm_csr_fused(
    const __half2* __restrict__ xh, __half2* __restrict__ yh,
    float* __restrict__ out, float scale, int writeY)
{
    int warp = (blockIdx.x * blockDim.x + threadIdx.x) >> 5;
    if (warp >= N_NODES) return;
    int lane = threadIdx.x & 31;

    int beg = __ldg(&g_rowptr[warp]);
    int end = __ldg(&g_rowptr[warp + 1]);

    float sx = 0.f, sy = 0.f;
    int j = beg;

    for (; j + 4 <= end; j += 4) {
        int2 cv0 = __ldg(&g_edges[j + 0]);
        int2 cv1 = __ldg(&g_edges[j + 1]);
        int2 cv2 = __ldg(&g_edges[j + 2]);
        int2 cv3 = __ldg(&g_edges[j + 3]);
        // 4 independent gathers in flight
        __half2 x0 = __ldg(xh + (((long long)cv0.x << 5) + lane));
        __half2 x1 = __ldg(xh + (((long long)cv1.x << 5) + lane));
        __half2 x2 = __ldg(xh + (((long long)cv2.x << 5) + lane));
        __half2 x3 = __ldg(xh + (((long long)cv3.x << 5) + lane));
        float v0 = __int_as_float(cv0.y);
        float v1 = __int_as_float(cv1.y);
        float v2 = __int_as_float(cv2.y);
        float v3 = __int_as_float(cv3.y);
        float2 f0 = __half22float2(x0);
        float2 f1 = __half22float2(x1);
        float2 f2 = __half22float2(x2);
        float2 f3 = __half22float2(x3);
        sx += v0 * f0.x + v1 * f1.x + v2 * f2.x + v3 * f3.x;
        sy += v0 * f0.y + v1 * f1.y + v2 * f2.y + v3 * f3.y;
    }
    for (; j < end; ++j) {
        int2 cv = __ldg(&g_edges[j]);
        __half2 xv = __ldg(xh + (((long long)cv.x << 5) + lane));
        float v = __int_as_float(cv.y);
        float2 xf = __half22float2(xv);
        sx += v * xf.x;
        sy += v * xf.y;
    }

    long long o = ((long long)warp << 5) + lane;
    if (writeY) yh[o] = __floats2half2_rn(sx, sy);

    float2 b = reinterpret_cast<float2*>(out)[o];
    float2 r;
    r.x = (b.x + sx) * scale;
    r.y = (b.y + sy) * scale;
    reinterpret_cast<float2*>(out)[o] = r;
}

extern "C" void kernel_launch(void* const* d_in, const int* in_sizes, int n_in,
                              void* d_out, int out_size)
{
    const float* user_emb = (const float*)d_in[0];
    const float* item_emb = (const float*)d_in[1];
    const int*   rows     = (const int*)d_in[2];
    const int*   cols     = (const int*)d_in[3];
    const float* vals     = (const float*)d_in[4];
    // d_in[5] = n_layers, fixed at 3 (compiled in as N_LAYERS)
    (void)in_sizes; (void)n_in; (void)out_size;

    float* out = (float*)d_out;

    __half2 *H0, *H1;
    int* counts;
    cudaGetSymbolAddress((void**)&H0, g_h0);
    cudaGetSymbolAddress((void**)&H1, g_h1);
    cudaGetSymbolAddress((void**)&counts, g_counts);

    // ---- CSR build ----
    cudaMemsetAsync(counts, 0, N_NODES * sizeof(int));
    {
        const int t = 256, b = (N_EDGES + t - 1) / t;
        hist_kernel<<<b, t>>>(rows);
    }
    scan1_kernel<<<N_SCAN_BLOCKS, SCAN_BLOCK>>>();
    scan2_kernel<<<1, 512>>>();
    {
        const int t = 256, b = (N_NODES + t - 1) / t;
        scan3_kernel<<<b, t>>>();
    }
    {
        const int t = 256, b = (N_EDGES + t - 1) / t;
        edge_scatter_kernel<<<b, t>>>(rows, cols, vals);
    }

    // ---- x0: out <- concat (fp32), H0 <- concat (half) ----
    {
        const int n2 = N_NODES * (DIM / 2);
        const int t = 256, b = (n2 + t - 1) / t;
        concat_kernel<<<b, t>>>(user_emb, item_emb, out, H0);
    }

    const int spmm_threads = 256;
    const long long spmm_total = (long long)N_NODES * 32;
    const int spmm_blocks = (int)((spmm_total + spmm_threads - 1) / spmm_threads);

    // Layer 0: gather H0 -> y H1;  out = out + s
    spmm_csr_fused<<<spmm_blocks, spmm_threads>>>(H0, H1, out, 1.0f, 1);
    // Layer 1: gather H1 -> y H0 (H0 dead);  out = out + s
    spmm_csr_fused<<<spmm_blocks, spmm_threads>>>(H1, H0, out, 1.0f, 1);
    // Layer 2: gather H0 -> no y;  out = (out + s) / 4
    spmm_csr_fused<<<spmm_blocks, spmm_threads>>>(H0, nullptr, out, 0.25f, 0);
}